// round 1
// baseline (speedup 1.0000x reference)
#include <cuda_runtime.h>
#include <cuda_bf16.h>

#define EPS 0.0001f
#define N_DIFFS 4194304

__device__ __forceinline__ float sigmoidf_(float x) {
    return 1.0f / (1.0f + __expf(-x));
}

__device__ __forceinline__ float piecewise_perf(float lb, float ub, float inv_den, float x) {
    // ramp = (ub - x) / (ub - lb + EPS); x<=lb -> 1; x>ub -> 0
    float ramp = (ub - x) * inv_den;
    float r = (x <= lb) ? 1.0f : ramp;
    r = (x > ub) ? 0.0f : r;
    return r;
}

__global__ void __launch_bounds__(256, 8)
perf_model_kernel(const float* __restrict__ bin_centers,
                  const int*   __restrict__ obs_idx,
                  const float* __restrict__ lb1p,
                  const float* __restrict__ ub1p,
                  const float* __restrict__ lb2p,
                  const float* __restrict__ ub2p,
                  const float* __restrict__ respp,
                  float* __restrict__ out)
{
    // uniform scalar prep (hoisted; identical across all threads)
    float a1 = __ldg(lb1p), b1 = __ldg(ub1p);
    float a2 = __ldg(lb2p), b2 = __ldg(ub2p);
    float nlb1 = sigmoidf_(fminf(a1, b1));
    float nub1 = sigmoidf_(fmaxf(a1, b1));
    float nlb2 = sigmoidf_(fminf(a2, b2));
    float nub2 = sigmoidf_(fmaxf(a2, b2));
    float r    = sigmoidf_(__ldg(respp));
    float inv1 = __frcp_rn(nub1 - nlb1 + EPS);
    float inv2 = __frcp_rn(nub2 - nlb2 + EPS);

    int t = blockIdx.x * blockDim.x + threadIdx.x;   // one thread = 4 rows
    int base_row = t * 4;
    if (base_row >= N_DIFFS) return;

    // 4 rows * 3 ints = 12 ints = 3 x int4, 16B aligned (offset 48*t bytes)
    const int4* p = reinterpret_cast<const int4*>(obs_idx + (long long)base_row * 3);
    int4 v0 = __ldg(p + 0);
    int4 v1 = __ldg(p + 1);
    int4 v2 = __ldg(p + 2);

    // row k uses elements (3k, 3k+1); element 3k+2 unused
    int i0a = v0.x, i0b = v0.y;   // row 0: e0, e1
    int i1a = v0.w, i1b = v1.x;   // row 1: e3, e4
    int i2a = v1.z, i2b = v1.w;   // row 2: e6, e7
    int i3a = v2.y, i3b = v2.z;   // row 3: e9, e10

    float x0a = __ldg(bin_centers + i0a), x0b = __ldg(bin_centers + i0b);
    float x1a = __ldg(bin_centers + i1a), x1b = __ldg(bin_centers + i1b);
    float x2a = __ldg(bin_centers + i2a), x2b = __ldg(bin_centers + i2b);
    float x3a = __ldg(bin_centers + i3a), x3b = __ldg(bin_centers + i3b);

    float4 o;
    o.x = piecewise_perf(nlb1, nub1, inv1, x0a) * piecewise_perf(nlb2, nub2, inv2, x0b) * r;
    o.y = piecewise_perf(nlb1, nub1, inv1, x1a) * piecewise_perf(nlb2, nub2, inv2, x1b) * r;
    o.z = piecewise_perf(nlb1, nub1, inv1, x2a) * piecewise_perf(nlb2, nub2, inv2, x2b) * r;
    o.w = piecewise_perf(nlb1, nub1, inv1, x3a) * piecewise_perf(nlb2, nub2, inv2, x3b) * r;

    reinterpret_cast<float4*>(out)[t] = o;
}

extern "C" void kernel_launch(void* const* d_in, const int* in_sizes, int n_in,
                              void* d_out, int out_size)
{
    // metadata order: bin_centers, obs_idx, lb1, ub1, lb2, ub2, resp
    const float* bin_centers = (const float*)d_in[0];
    const int*   obs_idx     = (const int*)  d_in[1];
    const float* lb1         = (const float*)d_in[2];
    const float* ub1         = (const float*)d_in[3];
    const float* lb2         = (const float*)d_in[4];
    const float* ub2         = (const float*)d_in[5];
    const float* resp        = (const float*)d_in[6];
    float* out = (float*)d_out;

    const int rows_per_thread = 4;
    const int threads = 256;
    int n_threads = N_DIFFS / rows_per_thread;           // 1,048,576
    int blocks = (n_threads + threads - 1) / threads;    // 4096

    perf_model_kernel<<<blocks, threads>>>(bin_centers, obs_idx,
                                           lb1, ub1, lb2, ub2, resp, out);
}